// round 1
// baseline (speedup 1.0000x reference)
#include <cuda_runtime.h>
#include <cstdint>

#define BB   32
#define TQQ  2000
#define TKK  512
#define PADK 516
#define EXNEG (-2000000)

// Scratch: softmax probabilities, padded column 0 = blank. ~132 MB device bss.
__device__ float g_probs[(size_t)BB * TQQ * PADK];
__device__ float g_loss[BB];

// ---------------------------------------------------------------------------
// Kernel 1: per-(b,t) softmax over padded keys j in [0, kl].
//   padded[0] = BLANK_LOGPROB = -1,  padded[j] = attn[b,t,j-1] for j=1..kl
//   P[b,t,j] = exp(padded[j] - logsumexp)
// One warp per row. Only rows t < ql are computed (DP never reads beyond).
// ---------------------------------------------------------------------------
__global__ __launch_bounds__(256) void probs_kernel(const float* __restrict__ attn,
                                                    const int* __restrict__ in_lens,
                                                    const int* __restrict__ out_lens) {
    int b    = blockIdx.y;
    int warp = threadIdx.x >> 5;
    int lane = threadIdx.x & 31;
    int t    = blockIdx.x * 8 + warp;
    if (t >= TQQ) return;
    int kl = min(max(in_lens[b], 1), TKK);
    int ql = min(max(out_lens[b], 1), TQQ);
    if (t >= ql) return;

    const float* row = attn + ((size_t)b * TQQ + t) * TKK;
    float v[17];
    float m = -1e30f;
#pragma unroll
    for (int k = 0; k < 17; k++) {
        int j = lane + 32 * k;
        float x = -1e30f;
        if (j <= kl) x = (j == 0) ? -1.0f : __ldg(row + j - 1);
        v[k] = x;
        m = fmaxf(m, x);
    }
#pragma unroll
    for (int o = 16; o; o >>= 1) m = fmaxf(m, __shfl_xor_sync(0xffffffffu, m, o));
    float s = 0.f;
#pragma unroll
    for (int k = 0; k < 17; k++) { v[k] = __expf(v[k] - m); s += v[k]; }
#pragma unroll
    for (int o = 16; o; o >>= 1) s += __shfl_xor_sync(0xffffffffu, s, o);
    float inv = 1.0f / s;

    float* out = g_probs + ((size_t)b * TQQ + t) * PADK;
#pragma unroll
    for (int k = 0; k < 17; k++) {
        int j = lane + 32 * k;
        if (j <= kl) out[j] = v[k] * inv;
    }
}

// ---------------------------------------------------------------------------
// Kernel 2: CTC forward recursion, probability domain, per-thread-pair
// block floating point. One block per batch element; thread i owns states
// (2i, 2i+1) as a float2 mantissa pair + int exponent.
//
//   even state 2i  :  A' = (A[2i]   + A[2i-1])            * P_blank
//   odd  state 2i+1:  A' = (A[2i+1] + A[2i]   + A[2i-1])  * P[label i+1]
//   (s=1 skip term excluded automatically via zero pad slot)
//
// Mixing across pairs scales the smaller contribution into the larger pair's
// exponent frame (flush at 2^-127 relative — locally negligible).
// ---------------------------------------------------------------------------
__global__ __launch_bounds__(544, 1) void dp_kernel(const int* __restrict__ in_lens,
                                                    const int* __restrict__ out_lens) {
    __shared__ float bufA[1032];
    __shared__ float bufB[1032];
    __shared__ int   exAr[516];
    __shared__ int   exBr[516];

    int b   = blockIdx.x;
    int tid = threadIdx.x;
    int kl  = min(max(in_lens[b], 1), TKK);
    int ql  = min(max(out_lens[b], 1), TQQ);

    for (int k = tid; k < 1032; k += 544) { bufA[k] = 0.f; bufB[k] = 0.f; }
    for (int k = tid; k < 516;  k += 544) { exAr[k] = EXNEG; exBr[k] = EXNEG; }
    __syncthreads();

    const float* prow0 = g_probs + (size_t)b * TQQ * PADK;
    if (tid == 0) {
        // alpha0: state 0 = P[0,0] (blank), state 1 = P[0,1]
        bufA[2] = prow0[0];
        bufA[3] = prow0[1];
        exAr[1] = 0;
    }
    __syncthreads();

    float2* cur = (float2*)bufA;   // cur[k] = states (2k-2, 2k-1); cur[0] = zero pad
    float2* nxt = (float2*)bufB;
    int* exc = exAr;               // exc[k] = exponent of pair owned by thread k-1
    int* exn = exBr;

    int  i      = tid;
    bool active = (i <= kl);
    int  exo    = (i == 0) ? 0 : EXNEG;   // register copy of own pair's exponent

    const float* prow = prow0 + PADK;     // row t=1
    float pf_o = 0.f, pf_b = 0.f;
    if (ql > 1) { pf_b = prow[0]; if (active) pf_o = __ldg(prow + i + 1); }

    for (int t = 1; t < ql; ++t) {
        float p_o = pf_o, p_b = pf_b;
        const float* nrow = prow + PADK;
        if (t + 1 < ql) { pf_b = nrow[0]; if (active) pf_o = __ldg(nrow + i + 1); }

        if (active) {
            float2 c0 = cur[i];       // neighbor pair: states (2i-2, 2i-1)
            float2 c1 = cur[i + 1];   // own pair:      states (2i,   2i+1)
            int en   = exc[i];
            int base = max(en, exo);
            int d0 = 127 + (en  - base); if (d0 < 0) d0 = 0;
            int d1 = 127 + (exo - base); if (d1 < 0) d1 = 0;
            float s0 = __int_as_float(d0 << 23);   // 2^(en-base),  flushed below 2^-127
            float s1 = __int_as_float(d1 << 23);   // 2^(exo-base)

            float a  = c0.y * s0;                  // A[2i-1] in base frame
            float se = fmaf(c1.x, s1, a);          // A[2i] + A[2i-1]
            float ne = se * p_b;                   // new even state 2i
            float no = fmaf(c1.y, s1, se) * p_o;   // new odd state 2i+1
            if (i >= kl) no = 0.f;                 // state 2kl+1 invalid

            float mm = fmaxf(ne, no);
            if (mm > 0.f) {
                int kk = ((__float_as_int(mm) >> 23) & 255) - 127;
                float sc = __int_as_float((127 - kk) << 23);  // exact 2^-kk
                ne *= sc; no *= sc;
                exo = base + kk;
            } else {
                ne = 0.f; no = 0.f;
                exo = EXNEG;
            }
            nxt[i + 1] = make_float2(ne, no);
            exn[i + 1] = exo;
        }
        __syncthreads();
        float2* tf = cur; cur = nxt; nxt = tf;
        int* te = exc; exc = exn; exn = te;
        prow = nrow;
    }

    if (tid == 0) {
        float* c   = (float*)cur;
        float mEnd = c[2 + 2 * kl];        // state 2kl   (pair kl, even slot)
        float mLab = c[2 + 2 * kl - 1];    // state 2kl-1 (pair kl-1, odd slot)
        int   eEnd = exc[kl + 1];
        int   eLab = exc[kl];
        double ll;
        if (mEnd == 0.f && mLab == 0.f) {
            ll = -1e9;   // matches reference NEG propagation (unreachable)
        } else {
            int eM = max((mEnd > 0.f) ? eEnd : EXNEG,
                         (mLab > 0.f) ? eLab : EXNEG);
            double sum = 0.0;
            if (mEnd > 0.f) sum += (double)mEnd * exp2((double)(eEnd - eM));
            if (mLab > 0.f) sum += (double)mLab * exp2((double)(eLab - eM));
            ll = log(sum) + (double)eM * 0.6931471805599453;
        }
        g_loss[b] = (float)(-ll / (double)kl);
    }
}

// ---------------------------------------------------------------------------
// Kernel 3: deterministic fixed-order mean over batch losses.
// ---------------------------------------------------------------------------
__global__ void finalize_kernel(float* out) {
    if (threadIdx.x == 0) {
        float s = 0.f;
        for (int b = 0; b < BB; b++) s += g_loss[b];
        out[0] = s / (float)BB;
    }
}

extern "C" void kernel_launch(void* const* d_in, const int* in_sizes, int n_in,
                              void* d_out, int out_size) {
    const float* attn     = (const float*)d_in[0];
    const int*   in_lens  = (const int*)d_in[1];
    const int*   out_lens = (const int*)d_in[2];

    probs_kernel<<<dim3((TQQ + 7) / 8, BB), 256>>>(attn, in_lens, out_lens);
    dp_kernel<<<BB, 544>>>(in_lens, out_lens);
    finalize_kernel<<<1, 32>>>((float*)d_out);
}

// round 2
// speedup vs baseline: 1.2174x; 1.2174x over previous
#include <cuda_runtime.h>
#include <cstdint>

#define BB   32
#define TQQ  2000
#define TKK  512
#define EXNEG (-2000000)
#define PBLANK 0.36787944117144233f   /* e^-1 (blank emission, unnormalized) */

__device__ float g_loss[BB];

// ---------------------------------------------------------------------------
// Fused CTC forward-sum in probability domain, unnormalized emissions.
// One block per batch element, 128 threads (4 warps). Thread i owns state
// pairs g = 4i..4i+3 (states 2g, 2g+1) as register float2 with ONE shared
// exponent per thread (block floating point). Pair 512 (state 1024 = 2*kl
// when kl==512) is carried as an extra scalar.
//
// Per time step:
//   even 2g  :  A' = (A[2g] + A[2g-1]) * e^-1
//   odd  2g+1:  A' = (A[2g+1] + A[2g] + A[2g-1]) * exp(x[t,g])   (g < kl)
// Softmax denominators Z_t are accumulated as per-warp partials in SMEM and
// folded in after the serial loop:  ll = log(A_end+A_lab) - sum_t log(Z_t).
// ---------------------------------------------------------------------------
__global__ __launch_bounds__(128, 1) void dp_kernel(const float* __restrict__ attn,
                                                    const int* __restrict__ in_lens,
                                                    const int* __restrict__ out_lens) {
    __shared__ float zrow[TQQ * 4];      // per-warp partial Z per row (32 KB)
    __shared__ float bv[2][4];           // warp-boundary halo mantissa (double buf)
    __shared__ int   be[2][4];           // warp-boundary halo exponent
    __shared__ float sm_even[513];
    __shared__ float sm_odd[513];
    __shared__ int   sm_ex[513];
    __shared__ float red[128];

    int b    = blockIdx.x;
    int tid  = threadIdx.x;
    int lane = tid & 31;
    int warp = tid >> 5;
    int kl = min(max(in_lens[b], 1), TKK);
    int ql = min(max(out_lens[b], 1), TQQ);

    const float* rowp = attn + (size_t)b * TQQ * TKK + tid * 4;

    bool mk0 = (tid * 4 + 0) < kl;
    bool mk1 = (tid * 4 + 1) < kl;
    bool mk2 = (tid * 4 + 2) < kl;
    bool mk3 = (tid * 4 + 3) < kl;

    // ---- row 0 ----
    float4 x = *(const float4*)rowp;
    float e0 = mk0 ? __expf(x.x) : 0.f;
    float e1 = mk1 ? __expf(x.y) : 0.f;
    float e2 = mk2 ? __expf(x.z) : 0.f;
    float e3 = mk3 ? __expf(x.w) : 0.f;
    float z = (e0 + e1) + (e2 + e3);
#pragma unroll
    for (int o = 16; o; o >>= 1) z += __shfl_xor_sync(0xffffffffu, z, o);
    if (lane == 0) zrow[warp] = z;

    float2 c[4];
#pragma unroll
    for (int j = 0; j < 4; j++) c[j] = make_float2(0.f, 0.f);
    float a1024 = 0.f;           // pair 512 even state (meaningful on tid 127)
    int   exo   = EXNEG;
    if (tid == 0) { c[0] = make_float2(PBLANK, e0); exo = 0; }

    if (lane == 31) { bv[1][warp] = c[3].y; be[1][warp] = exo; }

    float4 xn = make_float4(0.f, 0.f, 0.f, 0.f);
    if (ql > 1) xn = *(const float4*)(rowp + TKK);
    __syncthreads();

    // ---- serial time loop ----
    for (int t = 1; t < ql; ++t) {
        x = xn;
        if (t + 1 < ql) xn = *(const float4*)(rowp + (size_t)(t + 1) * TKK);

        e0 = mk0 ? __expf(x.x) : 0.f;
        e1 = mk1 ? __expf(x.y) : 0.f;
        e2 = mk2 ? __expf(x.z) : 0.f;
        e3 = mk3 ? __expf(x.w) : 0.f;
        z = (e0 + e1) + (e2 + e3);
#pragma unroll
        for (int o = 16; o; o >>= 1) z += __shfl_xor_sync(0xffffffffu, z, o);
        if (lane == 0) zrow[t * 4 + warp] = z;

        // halo: left neighbor's top odd mantissa + exponent (state 8i-1)
        float hm = __shfl_up_sync(0xffffffffu, c[3].y, 1);
        int   he = __shfl_up_sync(0xffffffffu, exo, 1);
        if (lane == 0) {
            if (warp == 0) { hm = 0.f; he = EXNEG; }
            else           { hm = bv[t & 1][warp - 1]; he = be[t & 1][warp - 1]; }
        }

        // align frames: base = max exponent; scale both sides by exact pow2
        int bse = max(exo, he);
        int d0 = 127 + (he  - bse); if (d0 < 0) d0 = 0;
        int d1 = 127 + (exo - bse); if (d1 < 0) d1 = 0;
        float sh = __int_as_float(d0 << 23);
        float so = __int_as_float(d1 << 23);

        float prev = hm * sh;     // A[2g-1] for first pair, in base frame
        float ne[4], no[4];
        {
            float ax, ay, se;
            ax = c[0].x * so; ay = c[0].y * so;
            se = ax + prev; ne[0] = se * PBLANK; no[0] = (ay + se) * e0; prev = ay;
            ax = c[1].x * so; ay = c[1].y * so;
            se = ax + prev; ne[1] = se * PBLANK; no[1] = (ay + se) * e1; prev = ay;
            ax = c[2].x * so; ay = c[2].y * so;
            se = ax + prev; ne[2] = se * PBLANK; no[2] = (ay + se) * e2; prev = ay;
            ax = c[3].x * so; ay = c[3].y * so;
            se = ax + prev; ne[3] = se * PBLANK; no[3] = (ay + se) * e3; prev = ay;
        }
        float n4 = (a1024 * so + prev) * PBLANK;   // pair 512 even (tid 127)

        // renormalize thread block-float frame
        float m = fmaxf(fmaxf(fmaxf(ne[0], no[0]), fmaxf(ne[1], no[1])),
                        fmaxf(fmaxf(ne[2], no[2]), fmaxf(ne[3], no[3])));
        m = fmaxf(m, n4);
        if (m > 0.f) {
            int kk = ((__float_as_int(m) >> 23) & 255) - 127;
            float sc = __int_as_float((127 - kk) << 23);
#pragma unroll
            for (int j = 0; j < 4; j++) c[j] = make_float2(ne[j] * sc, no[j] * sc);
            a1024 = n4 * sc;
            exo = bse + kk;
        } else {
#pragma unroll
            for (int j = 0; j < 4; j++) c[j] = make_float2(0.f, 0.f);
            a1024 = 0.f;
            exo = EXNEG;
        }

        if (lane == 31) { bv[(t + 1) & 1][warp] = c[3].y; be[(t + 1) & 1][warp] = exo; }
        __syncthreads();
    }

    // ---- epilogue ----
#pragma unroll
    for (int j = 0; j < 4; j++) {
        sm_even[tid * 4 + j] = c[j].x;
        sm_odd [tid * 4 + j] = c[j].y;
        sm_ex  [tid * 4 + j] = exo;
    }
    if (tid == 127) { sm_even[512] = a1024; sm_odd[512] = 0.f; sm_ex[512] = exo; }

    float lz = 0.f;
    for (int t = tid; t < ql; t += 128) {
        float zz = PBLANK + ((zrow[4 * t] + zrow[4 * t + 1]) +
                             (zrow[4 * t + 2] + zrow[4 * t + 3]));
        lz += __logf(zz);
    }
    red[tid] = lz;
    __syncthreads();
#pragma unroll
    for (int s = 64; s; s >>= 1) {
        if (tid < s) red[tid] += red[tid + s];
        __syncthreads();
    }

    if (tid == 0) {
        float mE = sm_even[kl];     int eE = sm_ex[kl];       // state 2kl
        float mL = sm_odd[kl - 1];  int eL = sm_ex[kl - 1];   // state 2kl-1
        double ll;
        if (mE == 0.f && mL == 0.f) {
            ll = -1e9;
        } else {
            int eM = max(mE > 0.f ? eE : EXNEG, mL > 0.f ? eL : EXNEG);
            double s2 = 0.0;
            if (mE > 0.f) s2 += (double)mE * exp2((double)(eE - eM));
            if (mL > 0.f) s2 += (double)mL * exp2((double)(eL - eM));
            ll = log(s2) + (double)eM * 0.6931471805599453;
        }
        ll -= (double)red[0];                 // subtract sum_t log Z_t
        g_loss[b] = (float)(-ll / (double)kl);
    }
}

__global__ void finalize_kernel(float* out) {
    if (threadIdx.x == 0) {
        float s = 0.f;
        for (int b = 0; b < BB; b++) s += g_loss[b];
        out[0] = s / (float)BB;
    }
}

extern "C" void kernel_launch(void* const* d_in, const int* in_sizes, int n_in,
                              void* d_out, int out_size) {
    const float* attn     = (const float*)d_in[0];
    const int*   in_lens  = (const int*)d_in[1];
    const int*   out_lens = (const int*)d_in[2];

    dp_kernel<<<BB, 128>>>(attn, in_lens, out_lens);
    finalize_kernel<<<1, 32>>>((float*)d_out);
}

// round 3
// speedup vs baseline: 2.5105x; 2.0622x over previous
#include <cuda_runtime.h>
#include <cstdint>

#define BB   32
#define TQQ  2000
#define TKK  512
#define EXNEG (-2000000)
#define PBLANK 0.36787944117144233f   /* e^-1 (blank emission, unnormalized) */
#define PFD  8                        /* prefetch depth (rows ahead) */

__device__ float g_loss[BB];
__device__ float g_logz[BB * TQQ];    // per-(b,t) log softmax denominator

// ---------------------------------------------------------------------------
// Kernel 1: per-row log partition  logZ = log(e^-1 + sum_{j<kl} exp(x[b,t,j]))
// One warp per row, only rows t < ql. Fully parallel, bandwidth-bound.
// ---------------------------------------------------------------------------
__global__ __launch_bounds__(256) void zlog_kernel(const float* __restrict__ attn,
                                                   const int* __restrict__ in_lens,
                                                   const int* __restrict__ out_lens) {
    int b    = blockIdx.y;
    int warp = threadIdx.x >> 5;
    int lane = threadIdx.x & 31;
    int t    = blockIdx.x * 8 + warp;
    if (t >= TQQ) return;
    int kl = min(max(in_lens[b], 1), TKK);
    int ql = min(max(out_lens[b], 1), TQQ);
    if (t >= ql) return;

    const float4* row = (const float4*)(attn + ((size_t)b * TQQ + t) * TKK);
    float s = 0.f;
#pragma unroll
    for (int k = 0; k < 4; k++) {
        float4 v = __ldg(row + lane + 32 * k);
        int j = 4 * (lane + 32 * k);
        float a0 = (j + 0 < kl) ? __expf(v.x) : 0.f;
        float a1 = (j + 1 < kl) ? __expf(v.y) : 0.f;
        float a2 = (j + 2 < kl) ? __expf(v.z) : 0.f;
        float a3 = (j + 3 < kl) ? __expf(v.w) : 0.f;
        s += (a0 + a1) + (a2 + a3);
    }
#pragma unroll
    for (int o = 16; o; o >>= 1) s += __shfl_xor_sync(0xffffffffu, s, o);
    if (lane == 0) g_logz[b * TQQ + t] = __logf(PBLANK + s);
}

// ---------------------------------------------------------------------------
// Kernel 2: CTC forward recursion, probability domain, unnormalized
// emissions, per-thread block floating point, 8-deep register prefetch.
// 128 threads/block, thread tid owns pairs g = 4*tid .. 4*tid+3.
// ---------------------------------------------------------------------------
__global__ __launch_bounds__(128, 1) void dp_kernel(const float* __restrict__ attn,
                                                    const int* __restrict__ in_lens,
                                                    const int* __restrict__ out_lens) {
    __shared__ float bvs[2][5];          // halo mantissa, +1 pad (slot 0 = zero)
    __shared__ int   bes[2][5];
    __shared__ float sm_even[513];
    __shared__ float sm_odd[513];
    __shared__ int   sm_ex[513];
    __shared__ float red[128];

    int b    = blockIdx.x;
    int tid  = threadIdx.x;
    int lane = tid & 31;
    int warp = tid >> 5;
    int kl = min(max(in_lens[b], 1), TKK);
    int ql = min(max(out_lens[b], 1), TQQ);

    const float4* base4 = (const float4*)(attn + (size_t)b * TQQ * TKK) + tid;

    bool mk0 = (tid * 4 + 0) < kl;
    bool mk1 = (tid * 4 + 1) < kl;
    bool mk2 = (tid * 4 + 2) < kl;
    bool mk3 = (tid * 4 + 3) < kl;

    if (tid < 2) {
        bvs[tid][0] = 0.f; bes[tid][0] = EXNEG;
    }

    // ---- row 0 init ----
    float4 x0 = __ldg(base4);
    float e00 = mk0 ? __expf(x0.x) : 0.f;

    float2 c[4];
#pragma unroll
    for (int j = 0; j < 4; j++) c[j] = make_float2(0.f, 0.f);
    float a1024 = 0.f;                   // pair-512 even state (tid 127 only)
    int   exo   = EXNEG;
    if (tid == 0) { c[0] = make_float2(PBLANK, e00); exo = 0; }

    if (lane == 31) { bvs[1][warp + 1] = c[3].y; bes[1][warp + 1] = exo; }

    // ---- prefetch pipeline: slot d holds row (t + d) where next t = 1 ----
    float4 xs0, xs1, xs2, xs3, xs4, xs5, xs6, xs7;
    {
        int qm = ql - 1;
        xs0 = __ldg(base4 + (size_t)min(1, qm) * 128);
        xs1 = __ldg(base4 + (size_t)min(2, qm) * 128);
        xs2 = __ldg(base4 + (size_t)min(3, qm) * 128);
        xs3 = __ldg(base4 + (size_t)min(4, qm) * 128);
        xs4 = __ldg(base4 + (size_t)min(5, qm) * 128);
        xs5 = __ldg(base4 + (size_t)min(6, qm) * 128);
        xs6 = __ldg(base4 + (size_t)min(7, qm) * 128);
        xs7 = __ldg(base4 + (size_t)min(8, qm) * 128);
    }
    __syncthreads();

#define DP_BODY(XV)                                                            \
    {                                                                          \
        float e0 = mk0 ? __expf((XV).x) : 0.f;                                 \
        float e1 = mk1 ? __expf((XV).y) : 0.f;                                 \
        float e2 = mk2 ? __expf((XV).z) : 0.f;                                 \
        float e3 = mk3 ? __expf((XV).w) : 0.f;                                 \
        float hm = __shfl_up_sync(0xffffffffu, c[3].y, 1);                     \
        int   he = __shfl_up_sync(0xffffffffu, exo, 1);                        \
        if (lane == 0) { hm = bvs[t & 1][warp]; he = bes[t & 1][warp]; }       \
        int bse = max(exo, he);                                                \
        int d0 = 127 + (he  - bse); if (d0 < 0) d0 = 0;                        \
        int d1 = 127 + (exo - bse); if (d1 < 0) d1 = 0;                        \
        float sh = __int_as_float(d0 << 23);                                   \
        float so = __int_as_float(d1 << 23);                                   \
        float prev = hm * sh;                                                  \
        float ne[4], no[4];                                                    \
        {                                                                      \
            float ax, ay, se;                                                  \
            ax = c[0].x * so; ay = c[0].y * so;                                \
            se = ax + prev; ne[0] = se * PBLANK; no[0] = (ay + se) * e0;       \
            prev = ay;                                                         \
            ax = c[1].x * so; ay = c[1].y * so;                                \
            se = ax + prev; ne[1] = se * PBLANK; no[1] = (ay + se) * e1;       \
            prev = ay;                                                         \
            ax = c[2].x * so; ay = c[2].y * so;                                \
            se = ax + prev; ne[2] = se * PBLANK; no[2] = (ay + se) * e2;       \
            prev = ay;                                                         \
            ax = c[3].x * so; ay = c[3].y * so;                                \
            se = ax + prev; ne[3] = se * PBLANK; no[3] = (ay + se) * e3;       \
            prev = ay;                                                         \
        }                                                                      \
        float n4 = (a1024 * so + prev) * PBLANK;                               \
        float m = fmaxf(fmaxf(fmaxf(ne[0], no[0]), fmaxf(ne[1], no[1])),       \
                        fmaxf(fmaxf(ne[2], no[2]), fmaxf(ne[3], no[3])));      \
        m = fmaxf(m, n4);                                                      \
        if (m > 0.f) {                                                         \
            int kk = ((__float_as_int(m) >> 23) & 255) - 127;                  \
            float sc = __int_as_float((127 - kk) << 23);                       \
            c[0] = make_float2(ne[0] * sc, no[0] * sc);                        \
            c[1] = make_float2(ne[1] * sc, no[1] * sc);                        \
            c[2] = make_float2(ne[2] * sc, no[2] * sc);                        \
            c[3] = make_float2(ne[3] * sc, no[3] * sc);                        \
            a1024 = n4 * sc;                                                   \
            exo = bse + kk;                                                    \
        } else {                                                               \
            c[0] = c[1] = c[2] = c[3] = make_float2(0.f, 0.f);                 \
            a1024 = 0.f;                                                       \
            exo = EXNEG;                                                       \
        }                                                                      \
        if (lane == 31) {                                                      \
            bvs[(t + 1) & 1][warp + 1] = c[3].y;                               \
            bes[(t + 1) & 1][warp + 1] = exo;                                  \
        }                                                                      \
        __syncthreads();                                                       \
        ++t;                                                                   \
    }

#define DP_STEP(SLOT)                                                          \
    {                                                                          \
        float4 xcur = SLOT;                                                    \
        SLOT = __ldg(base4 + (size_t)min(t + PFD, ql - 1) * 128);              \
        DP_BODY(xcur)                                                          \
    }

    int t = 1;
    while (t + (PFD - 1) < ql) {
        DP_STEP(xs0) DP_STEP(xs1) DP_STEP(xs2) DP_STEP(xs3)
        DP_STEP(xs4) DP_STEP(xs5) DP_STEP(xs6) DP_STEP(xs7)
    }
    while (t < ql) {
        float4 xcur = __ldg(base4 + (size_t)t * 128);
        DP_BODY(xcur)
    }

    // ---- epilogue ----
#pragma unroll
    for (int j = 0; j < 4; j++) {
        sm_even[tid * 4 + j] = c[j].x;
        sm_odd [tid * 4 + j] = c[j].y;
        sm_ex  [tid * 4 + j] = exo;
    }
    if (tid == 127) { sm_even[512] = a1024; sm_odd[512] = 0.f; sm_ex[512] = exo; }

    float lz = 0.f;
    for (int tt = tid; tt < ql; tt += 128) lz += g_logz[b * TQQ + tt];
    red[tid] = lz;
    __syncthreads();
#pragma unroll
    for (int s = 64; s; s >>= 1) {
        if (tid < s) red[tid] += red[tid + s];
        __syncthreads();
    }

    if (tid == 0) {
        float mE = sm_even[kl];     int eE = sm_ex[kl];       // state 2kl
        float mL = sm_odd[kl - 1];  int eL = sm_ex[kl - 1];   // state 2kl-1
        double ll;
        if (mE == 0.f && mL == 0.f) {
            ll = -1e9;
        } else {
            int eM = max(mE > 0.f ? eE : EXNEG, mL > 0.f ? eL : EXNEG);
            double s2 = 0.0;
            if (mE > 0.f) s2 += (double)mE * exp2((double)(eE - eM));
            if (mL > 0.f) s2 += (double)mL * exp2((double)(eL - eM));
            ll = log(s2) + (double)eM * 0.6931471805599453;
        }
        ll -= (double)red[0];                 // subtract sum_t log Z_t
        g_loss[b] = (float)(-ll / (double)kl);
    }
}

__global__ void finalize_kernel(float* out) {
    if (threadIdx.x == 0) {
        float s = 0.f;
        for (int b = 0; b < BB; b++) s += g_loss[b];
        out[0] = s / (float)BB;
    }
}

extern "C" void kernel_launch(void* const* d_in, const int* in_sizes, int n_in,
                              void* d_out, int out_size) {
    const float* attn     = (const float*)d_in[0];
    const int*   in_lens  = (const int*)d_in[1];
    const int*   out_lens = (const int*)d_in[2];

    zlog_kernel<<<dim3((TQQ + 7) / 8, BB), 256>>>(attn, in_lens, out_lens);
    dp_kernel<<<BB, 128>>>(attn, in_lens, out_lens);
    finalize_kernel<<<1, 32>>>((float*)d_out);
}

// round 4
// speedup vs baseline: 4.6940x; 1.8698x over previous
#include <cuda_runtime.h>
#include <cstdint>

#define BB   32
#define TQQ  2000
#define TKK  512
#define EXNEG (-2000000)
#define PBLANK 0.36787944117144233f   /* e^-1 */
#define L2E 1.4426950408889634f
#define FULLW 0xffffffffu

__device__ float    g_loss[BB];
__device__ float    g_logz[BB * TQQ];
__device__ unsigned g_ctr = 0;

__device__ __forceinline__ float ex2f_(float x) {
    float r;
    asm("ex2.approx.ftz.f32 %0, %1;" : "=f"(r) : "f"(x));
    return r;
}

// ---------------------------------------------------------------------------
// Kernel 1: per-row log partition  logZ = log(e^-1 + sum_{j<kl} exp(x))
// ---------------------------------------------------------------------------
__global__ __launch_bounds__(256) void zlog_kernel(const float* __restrict__ attn,
                                                   const int* __restrict__ in_lens,
                                                   const int* __restrict__ out_lens) {
    int b    = blockIdx.y;
    int warp = threadIdx.x >> 5;
    int lane = threadIdx.x & 31;
    int t    = blockIdx.x * 8 + warp;
    if (t >= TQQ) return;
    int kl = min(max(in_lens[b], 1), TKK);
    int ql = min(max(out_lens[b], 1), TQQ);
    if (t >= ql) return;

    const float4* row = (const float4*)(attn + ((size_t)b * TQQ + t) * TKK);
    float s = 0.f;
#pragma unroll
    for (int k = 0; k < 4; k++) {
        float4 v = __ldg(row + lane + 32 * k);
        int j = 4 * (lane + 32 * k);
        float a0 = (j + 0 < kl) ? __expf(v.x) : 0.f;
        float a1 = (j + 1 < kl) ? __expf(v.y) : 0.f;
        float a2 = (j + 2 < kl) ? __expf(v.z) : 0.f;
        float a3 = (j + 3 < kl) ? __expf(v.w) : 0.f;
        s += (a0 + a1) + (a2 + a3);
    }
#pragma unroll
    for (int o = 16; o; o >>= 1) s += __shfl_xor_sync(FULLW, s, o);
    if (lane == 0) g_logz[b * TQQ + t] = __logf(PBLANK + s);
}

// ---------------------------------------------------------------------------
// Kernel 2: CTC forward recursion. B-domain (blank folded out), 4 steps per
// exchange/barrier, per-thread block floating point, 8-row prefetch.
// 128 threads/block; thread i owns states 8i..8i+7 (pairs 4i..4i+3).
// ---------------------------------------------------------------------------
__global__ __launch_bounds__(128, 1) void dp_kernel(const float* __restrict__ attn,
                                                    const int* __restrict__ in_lens,
                                                    const int* __restrict__ out_lens,
                                                    float* __restrict__ out) {
    __shared__ float xch[2][5][16];   // [parity][warp+1][slot] slot0 = zeros
    __shared__ float sm_even[513];
    __shared__ float sm_odd[513];
    __shared__ int   sm_ex[513];
    __shared__ float red[128];

    int b    = blockIdx.x;
    int tid  = threadIdx.x;
    int lane = tid & 31;
    int warp = tid >> 5;
    int kl = min(max(in_lens[b], 1), TKK);
    int ql = min(max(out_lens[b], 1), TQQ);

    const float4* base4 = (const float4*)(attn + (size_t)b * TQQ * TKK) + tid;

    bool mk0 = (tid * 4 + 0) < kl;
    bool mk1 = (tid * 4 + 1) < kl;
    bool mk2 = (tid * 4 + 2) < kl;
    bool mk3 = (tid * 4 + 3) < kl;

    if (tid < 2) {
#pragma unroll
        for (int k = 0; k < 16; k++) xch[tid][0][k] = 0.f;
        xch[tid][0][8] = __int_as_float(EXNEG);
    }

    // ---- row 0 init (B_0 = A_0) ----
    float4 x0 = __ldg(base4);
    float c8[8];
#pragma unroll
    for (int k = 0; k < 8; k++) c8[k] = 0.f;
    float a1024 = 0.f;
    int   exo   = EXNEG;
    if (tid == 0) { c8[0] = PBLANK; c8[1] = __expf(x0.x); exo = 0; }

    // ---- prefetch rows 1..8 ----
    int qm = ql - 1;
    float4 xs0 = __ldg(base4 + (size_t)min(1, qm) * 128);
    float4 xs1 = __ldg(base4 + (size_t)min(2, qm) * 128);
    float4 xs2 = __ldg(base4 + (size_t)min(3, qm) * 128);
    float4 xs3 = __ldg(base4 + (size_t)min(4, qm) * 128);
    float4 xs4 = __ldg(base4 + (size_t)min(5, qm) * 128);
    float4 xs5 = __ldg(base4 + (size_t)min(6, qm) * 128);
    float4 xs6 = __ldg(base4 + (size_t)min(7, qm) * 128);
    float4 xs7 = __ldg(base4 + (size_t)min(8, qm) * 128);

    int t = 1;

#define EMIT(XC, MK) ((MK) ? ex2f_(fmaf((XC), L2E, L2E)) : 0.f)
#define PAIRS(DST, SRC, J, EM)                                                 \
    { float se_ = SRC[J] + SRC[J - 1]; DST[J] = se_;                           \
      DST[J + 1] = (SRC[J + 1] + se_) * (EM); }

#define GROUP(S0, S1, S2, S3, REFILL, GUARDED)                                 \
    {                                                                          \
        float e00 = EMIT((S0).x, mk0), e01 = EMIT((S0).y, mk1);                \
        float e02 = EMIT((S0).z, mk2), e03 = EMIT((S0).w, mk3);                \
        float e10 = EMIT((S1).x, mk0), e11 = EMIT((S1).y, mk1);                \
        float e12 = EMIT((S1).z, mk2), e13 = EMIT((S1).w, mk3);                \
        float e20 = EMIT((S2).x, mk0), e21 = EMIT((S2).y, mk1);                \
        float e22 = EMIT((S2).z, mk2), e23 = EMIT((S2).w, mk3);                \
        float e30 = EMIT((S3).x, mk0), e31 = EMIT((S3).y, mk1);                \
        float e32 = EMIT((S3).z, mk2), e33 = EMIT((S3).w, mk3);                \
        if (REFILL) {                                                          \
            (S0) = __ldg(base4 + (size_t)min(t + 8,  qm) * 128);               \
            (S1) = __ldg(base4 + (size_t)min(t + 9,  qm) * 128);               \
            (S2) = __ldg(base4 + (size_t)min(t + 10, qm) * 128);               \
            (S3) = __ldg(base4 + (size_t)min(t + 11, qm) * 128);               \
        }                                                                      \
        int p_ = ((t - 1) >> 2) & 1;                                           \
        if (lane == 31) {                                                      \
            float* wb = xch[p_][warp + 1];                                     \
            wb[0] = c8[0]; wb[1] = c8[1]; wb[2] = c8[2]; wb[3] = c8[3];        \
            wb[4] = c8[4]; wb[5] = c8[5]; wb[6] = c8[6]; wb[7] = c8[7];        \
            wb[8] = __int_as_float(exo);                                       \
            wb[9] = e01; wb[10] = e02; wb[11] = e03;                           \
            wb[12] = e12; wb[13] = e13; wb[14] = e23;                          \
        }                                                                      \
        __syncthreads();                                                       \
        float h_[8]; int he_;                                                  \
        float f01, f02, f03, f12, f13, f23;                                    \
        h_[0] = __shfl_up_sync(FULLW, c8[0], 1);                               \
        h_[1] = __shfl_up_sync(FULLW, c8[1], 1);                               \
        h_[2] = __shfl_up_sync(FULLW, c8[2], 1);                               \
        h_[3] = __shfl_up_sync(FULLW, c8[3], 1);                               \
        h_[4] = __shfl_up_sync(FULLW, c8[4], 1);                               \
        h_[5] = __shfl_up_sync(FULLW, c8[5], 1);                               \
        h_[6] = __shfl_up_sync(FULLW, c8[6], 1);                               \
        h_[7] = __shfl_up_sync(FULLW, c8[7], 1);                               \
        he_  = __shfl_up_sync(FULLW, exo, 1);                                  \
        f01 = __shfl_up_sync(FULLW, e01, 1);                                   \
        f02 = __shfl_up_sync(FULLW, e02, 1);                                   \
        f03 = __shfl_up_sync(FULLW, e03, 1);                                   \
        f12 = __shfl_up_sync(FULLW, e12, 1);                                   \
        f13 = __shfl_up_sync(FULLW, e13, 1);                                   \
        f23 = __shfl_up_sync(FULLW, e23, 1);                                   \
        if (lane == 0) {                                                       \
            const float* rb = xch[p_][warp];                                   \
            h_[0] = rb[0]; h_[1] = rb[1]; h_[2] = rb[2]; h_[3] = rb[3];        \
            h_[4] = rb[4]; h_[5] = rb[5]; h_[6] = rb[6]; h_[7] = rb[7];        \
            he_ = __float_as_int(rb[8]);                                       \
            f01 = rb[9]; f02 = rb[10]; f03 = rb[11];                           \
            f12 = rb[12]; f13 = rb[13]; f23 = rb[14];                          \
        }                                                                      \
        int bse = max(exo, he_);                                               \
        int d0_ = 127 + (he_ - bse); if (d0_ < 0) d0_ = 0;                     \
        int d1_ = 127 + (exo - bse); if (d1_ < 0) d1_ = 0;                     \
        float sh_ = __int_as_float(d0_ << 23);                                 \
        float so_ = __int_as_float(d1_ << 23);                                 \
        float A_[16], B_[16];                                                  \
        A_[0] = h_[0] * sh_; A_[1] = h_[1] * sh_;                              \
        A_[2] = h_[2] * sh_; A_[3] = h_[3] * sh_;                              \
        A_[4] = h_[4] * sh_; A_[5] = h_[5] * sh_;                              \
        A_[6] = h_[6] * sh_; A_[7] = h_[7] * sh_;                              \
        A_[8]  = c8[0] * so_; A_[9]  = c8[1] * so_;                            \
        A_[10] = c8[2] * so_; A_[11] = c8[3] * so_;                            \
        A_[12] = c8[4] * so_; A_[13] = c8[5] * so_;                            \
        A_[14] = c8[6] * so_; A_[15] = c8[7] * so_;                            \
        float n4 = a1024 * so_;                                                \
        if (!(GUARDED) || (t + 0 < ql)) {                                      \
            PAIRS(B_, A_, 2, f01) PAIRS(B_, A_, 4, f02) PAIRS(B_, A_, 6, f03)  \
            PAIRS(B_, A_, 8, e00) PAIRS(B_, A_, 10, e01)                       \
            PAIRS(B_, A_, 12, e02) PAIRS(B_, A_, 14, e03)                      \
            n4 = n4 + A_[15];                                                  \
        } else {                                                               \
            _Pragma("unroll")                                                  \
            for (int j_ = 2; j_ < 16; j_++) B_[j_] = A_[j_];                   \
        }                                                                      \
        if (!(GUARDED) || (t + 1 < ql)) {                                      \
            PAIRS(A_, B_, 4, f12) PAIRS(A_, B_, 6, f13)                        \
            PAIRS(A_, B_, 8, e10) PAIRS(A_, B_, 10, e11)                       \
            PAIRS(A_, B_, 12, e12) PAIRS(A_, B_, 14, e13)                      \
            n4 = n4 + B_[15];                                                  \
        } else {                                                               \
            _Pragma("unroll")                                                  \
            for (int j_ = 4; j_ < 16; j_++) A_[j_] = B_[j_];                   \
        }                                                                      \
        if (!(GUARDED) || (t + 2 < ql)) {                                      \
            PAIRS(B_, A_, 6, f23)                                              \
            PAIRS(B_, A_, 8, e20) PAIRS(B_, A_, 10, e21)                       \
            PAIRS(B_, A_, 12, e22) PAIRS(B_, A_, 14, e23)                      \
            n4 = n4 + A_[15];                                                  \
        } else {                                                               \
            _Pragma("unroll")                                                  \
            for (int j_ = 6; j_ < 16; j_++) B_[j_] = A_[j_];                   \
        }                                                                      \
        if (!(GUARDED) || (t + 3 < ql)) {                                      \
            PAIRS(A_, B_, 8, e30) PAIRS(A_, B_, 10, e31)                       \
            PAIRS(A_, B_, 12, e32) PAIRS(A_, B_, 14, e33)                      \
            n4 = n4 + B_[15];                                                  \
        } else {                                                               \
            _Pragma("unroll")                                                  \
            for (int j_ = 8; j_ < 16; j_++) A_[j_] = B_[j_];                   \
        }                                                                      \
        float m_ = fmaxf(fmaxf(fmaxf(A_[8], A_[9]), fmaxf(A_[10], A_[11])),    \
                         fmaxf(fmaxf(A_[12], A_[13]), fmaxf(A_[14], A_[15]))); \
        m_ = fmaxf(m_, n4);                                                    \
        int kk_ = ((__float_as_int(m_) >> 23) & 255) - 127;                    \
        float sc_ = __int_as_float((127 - kk_) << 23);                         \
        c8[0] = A_[8]  * sc_; c8[1] = A_[9]  * sc_;                            \
        c8[2] = A_[10] * sc_; c8[3] = A_[11] * sc_;                            \
        c8[4] = A_[12] * sc_; c8[5] = A_[13] * sc_;                            \
        c8[6] = A_[14] * sc_; c8[7] = A_[15] * sc_;                            \
        a1024 = n4 * sc_;                                                      \
        exo = (m_ > 0.f) ? (bse + kk_) : EXNEG;                                \
        t += 4;                                                                \
    }

    while (t + 7 < ql) {
        GROUP(xs0, xs1, xs2, xs3, 1, 0)
        GROUP(xs4, xs5, xs6, xs7, 1, 0)
    }
    if (t + 3 < ql) {
        GROUP(xs0, xs1, xs2, xs3, 0, 0)
        if (t < ql) { GROUP(xs4, xs5, xs6, xs7, 0, 1) }
    } else if (t < ql) {
        GROUP(xs0, xs1, xs2, xs3, 0, 1)
    }

    // ---- epilogue ----
#pragma unroll
    for (int k = 0; k < 4; k++) {
        sm_even[tid * 4 + k] = c8[2 * k];
        sm_odd [tid * 4 + k] = c8[2 * k + 1];
        sm_ex  [tid * 4 + k] = exo;
    }
    if (tid == 127) { sm_even[512] = a1024; sm_odd[512] = 0.f; sm_ex[512] = exo; }

    float lz = 0.f;
    for (int tt = tid; tt < ql; tt += 128) lz += g_logz[b * TQQ + tt];
    red[tid] = lz;
    __syncthreads();
#pragma unroll
    for (int s = 64; s; s >>= 1) {
        if (tid < s) red[tid] += red[tid + s];
        __syncthreads();
    }

    if (tid == 0) {
        float mE = sm_even[kl];     int eE = sm_ex[kl];       // state 2kl
        float mL = sm_odd[kl - 1];  int eL = sm_ex[kl - 1];   // state 2kl-1
        double ll;
        if (mE == 0.f && mL == 0.f) {
            ll = -1e9;
        } else {
            int eM = max(mE > 0.f ? eE : EXNEG, mL > 0.f ? eL : EXNEG);
            double s2 = 0.0;
            if (mE > 0.f) s2 += (double)mE * exp2((double)(eE - eM));
            if (mL > 0.f) s2 += (double)mL * exp2((double)(eL - eM));
            ll = log(s2) + (double)eM * 0.6931471805599453;
        }
        ll -= (double)red[0];          // - sum_t log Z_t
        ll -= (double)(ql - 1);        // undo B = A * e^t rescale
        g_loss[b] = (float)(-ll / (double)kl);

        __threadfence();
        unsigned prev = atomicAdd(&g_ctr, 1u);
        if (prev == BB - 1) {
            g_ctr = 0;
            __threadfence();
            float s = 0.f;
            for (int bb = 0; bb < BB; bb++) s += g_loss[bb];
            out[0] = s / (float)BB;
        }
    }
}

extern "C" void kernel_launch(void* const* d_in, const int* in_sizes, int n_in,
                              void* d_out, int out_size) {
    const float* attn     = (const float*)d_in[0];
    const int*   in_lens  = (const int*)d_in[1];
    const int*   out_lens = (const int*)d_in[2];

    zlog_kernel<<<dim3((TQQ + 7) / 8, BB), 256>>>(attn, in_lens, out_lens);
    dp_kernel<<<BB, 128>>>(attn, in_lens, out_lens, (float*)d_out);
}